// round 15
// baseline (speedup 1.0000x reference)
#include <cuda_runtime.h>
#include <cuda_bf16.h>
#include <cstdint>

#define Bdim 4
#define Hdim 16
#define Ndim 2048
#define Ddim 64
#define TOTE (Bdim*Hdim*Ndim*Ddim)   // 8388608

// bf16 scratch in [B, H, N, D] layout
__device__ __align__(16) __nv_bfloat16 g_q[TOTE];
__device__ __align__(16) __nv_bfloat16 g_k[TOTE];
__device__ __align__(16) __nv_bfloat16 g_v[TOTE];
// per-row -log2(denominator): [bh][n]
__device__ __align__(16) float g_l[Bdim*Hdim*Ndim];

// ---------------- converter: [B,N,H*D] f32 -> [B,H,N,D] bf16 ----------------
__global__ void cvt_kernel(const float* __restrict__ q,
                           const float* __restrict__ k,
                           const float* __restrict__ v) {
    long i4 = (long)blockIdx.x * blockDim.x + threadIdx.x;
    long o = i4 * 4;
    if (o >= TOTE) return;
    int d = (int)(o & 63);
    int n = (int)((o >> 6) & 2047);
    int h = (int)((o >> 17) & 15);
    int b = (int)(o >> 21);
    long in_off = (((long)b * Ndim + n) * Hdim + h) * Ddim + d;

    float4 fq = *(const float4*)(q + in_off);
    float4 fk = *(const float4*)(k + in_off);
    float4 fv = *(const float4*)(v + in_off);

    __nv_bfloat162 q0 = __floats2bfloat162_rn(fq.x, fq.y);
    __nv_bfloat162 q1 = __floats2bfloat162_rn(fq.z, fq.w);
    __nv_bfloat162 k0 = __floats2bfloat162_rn(fk.x, fk.y);
    __nv_bfloat162 k1 = __floats2bfloat162_rn(fk.z, fk.w);
    __nv_bfloat162 v0 = __floats2bfloat162_rn(fv.x, fv.y);
    __nv_bfloat162 v1 = __floats2bfloat162_rn(fv.z, fv.w);

    uint2 uq = { *(uint32_t*)&q0, *(uint32_t*)&q1 };
    uint2 uk = { *(uint32_t*)&k0, *(uint32_t*)&k1 };
    uint2 uv = { *(uint32_t*)&v0, *(uint32_t*)&v1 };
    *(uint2*)(g_q + o) = uq;
    *(uint2*)(g_k + o) = uk;
    *(uint2*)(g_v + o) = uv;
}

// ---------------- helpers ----------------
__device__ __forceinline__ unsigned su(const void* p) {
    return (unsigned)__cvta_generic_to_shared(p);
}
__device__ __forceinline__ void ldsm_x4(uint32_t r[4], unsigned addr) {
    asm volatile("ldmatrix.sync.aligned.m8n8.x4.shared.b16 {%0,%1,%2,%3}, [%4];"
                 : "=r"(r[0]), "=r"(r[1]), "=r"(r[2]), "=r"(r[3]) : "r"(addr));
}
__device__ __forceinline__ void ldsm_x4_t(uint32_t r[4], unsigned addr) {
    asm volatile("ldmatrix.sync.aligned.m8n8.x4.trans.shared.b16 {%0,%1,%2,%3}, [%4];"
                 : "=r"(r[0]), "=r"(r[1]), "=r"(r[2]), "=r"(r[3]) : "r"(addr));
}
__device__ __forceinline__ void mma16816(float c[4],
                                         uint32_t a0, uint32_t a1, uint32_t a2, uint32_t a3,
                                         uint32_t b0, uint32_t b1) {
    asm volatile(
        "mma.sync.aligned.m16n8k16.row.col.f32.bf16.bf16.f32 "
        "{%0,%1,%2,%3}, {%4,%5,%6,%7}, {%8,%9}, {%0,%1,%2,%3};"
        : "+f"(c[0]), "+f"(c[1]), "+f"(c[2]), "+f"(c[3])
        : "r"(a0), "r"(a1), "r"(a2), "r"(a3), "r"(b0), "r"(b1));
}
__device__ __forceinline__ float ex2f(float x) {
    float y; asm("ex2.approx.f32 %0, %1;" : "=f"(y) : "f"(x)); return y;
}
__device__ __forceinline__ uint32_t pack_bf2(float a, float b) {
    __nv_bfloat162 t = __floats2bfloat162_rn(a, b);
    return *reinterpret_cast<uint32_t*>(&t);
}
__device__ __forceinline__ float rb(float x) {
    return __bfloat162float(__float2bfloat16(x));
}
// packed f32x2 ops (FFMA2-class, fma pipe, 2 lanes per issue)
__device__ __forceinline__ uint64_t bfpair(uint32_t u) {   // bf16x2 word -> f32 pair
    uint64_t p;
    asm("{\n\t.reg .b32 lo, hi;\n\t"
        "shl.b32 lo, %1, 16;\n\t"
        "and.b32 hi, %1, 0xFFFF0000;\n\t"
        "mov.b64 %0, {lo, hi};\n\t}"
        : "=l"(p) : "r"(u));
    return p;
}
__device__ __forceinline__ uint64_t pk2(float x, float y) {
    uint64_t p; asm("mov.b64 %0, {%1, %2};" : "=l"(p) : "f"(x), "f"(y)); return p;
}
__device__ __forceinline__ void up2(uint64_t p, float& x, float& y) {
    asm("mov.b64 {%0, %1}, %2;" : "=f"(x), "=f"(y) : "l"(p));
}
__device__ __forceinline__ uint64_t mul2(uint64_t a, uint64_t b) {
    uint64_t r; asm("mul.rn.f32x2 %0, %1, %2;" : "=l"(r) : "l"(a), "l"(b)); return r;
}
__device__ __forceinline__ uint64_t fma2(uint64_t a, uint64_t b, uint64_t c) {
    uint64_t r; asm("fma.rn.f32x2 %0, %1, %2, %3;" : "=l"(r) : "l"(a), "l"(b), "l"(c)); return r;
}
__device__ __forceinline__ uint64_t add2(uint64_t a, uint64_t b) {
    uint64_t r; asm("add.rn.f32x2 %0, %1, %2;" : "=l"(r) : "l"(a), "l"(b)); return r;
}
__device__ __forceinline__ void cp_async16s(unsigned smem, const void* gmem) {
    asm volatile("cp.async.cg.shared.global [%0], [%1], 16;\n"
                 :: "r"(smem), "l"(gmem));
}
#define CP_COMMIT() asm volatile("cp.async.commit_group;\n" ::: "memory")
#define CP_WAIT0()  asm volatile("cp.async.wait_group 0;\n" ::: "memory")

constexpr int SQ = 72;    // smem row stride (bf16); conflict-free for ldsm pattern
constexpr int QELEMS = 128 * SQ;
constexpr int TELEMS = 64 * SQ;
constexpr int SMEMB1 = (QELEMS + 2 * TELEMS) * 2;   // 36864
constexpr int SMEMB2 = (QELEMS + 4 * TELEMS) * 2;   // 55296
constexpr int TBYTES = 64 * Ddim * 2;               // 8192
constexpr unsigned CH16 = (unsigned)(16 * SQ * 2);  // 16-row smem chunk

// scale * log2(e)
#define SCL2 0.18033688011112042f

// ===================== PASS 1: denominators (M=32 per warp) =====================
__global__ __launch_bounds__(128, 5) void pass1_kernel() {
    extern __shared__ __align__(16) __nv_bfloat16 smem[];
    __nv_bfloat16* sQ  = smem;
    __nv_bfloat16* sK0 = smem + QELEMS;
    __nv_bfloat16* sK1 = sK0 + TELEMS;

    const int tid  = threadIdx.x;
    const int warp = tid >> 5;     // 0..3, each owns 32 rows
    const int lane = tid & 31;
    const int mblk = blockIdx.x;
    const int bh   = blockIdx.y;

    const __nv_bfloat16* Qg = g_q + (size_t)bh * Ndim * Ddim + (size_t)mblk * 128 * Ddim;
    const __nv_bfloat16* Kg = g_k + (size_t)bh * Ndim * Ddim;

    const int krow = lane & 7;
    const int kc8  = (lane >> 3) & 3;
    const unsigned kfragoff = (unsigned)((krow * SQ + kc8 * 8) * 2);
    const unsigned kA[2] = { su(sK0) + kfragoff, su(sK1) + kfragoff };

    const int srow = tid >> 3, scol = tid & 7;   // srow 0..15
    const unsigned stoff = (unsigned)((srow * SQ + scol * 8) * 2);
    const unsigned dK[2] = { su(sK0) + stoff, su(sK1) + stoff };
    const char* gKt = (const char*)Kg + tid * 16;

    const uint64_t SCL2P = pk2(SCL2, SCL2);

    // stage Q (8 chunks) + K0 (4 chunks)
    {
        const char* src = (const char*)Qg + tid * 16;
        unsigned qdst = su(sQ) + stoff;
        #pragma unroll
        for (int it = 0; it < 8; it++)
            cp_async16s(qdst + it * CH16, src + it * 2048);
        #pragma unroll
        for (int it = 0; it < 4; it++)
            cp_async16s(dK[0] + it * CH16, gKt + it * 2048);
        CP_COMMIT();
    }
    CP_WAIT0();
    __syncthreads();

    // Q fragments: 2 m16-frags per warp
    uint32_t qa[2][4][4];
    #pragma unroll
    for (int f = 0; f < 2; f++) {
        int rofs = warp * 32 + f * 16 + (lane & 15);
        int cofs = (lane & 16) ? 8 : 0;
        unsigned qaddr = su(sQ) + (unsigned)((rofs * SQ + cofs) * 2);
        #pragma unroll
        for (int kk = 0; kk < 4; kk++)
            ldsm_x4(qa[f][kk], qaddr + kk * 32);
    }

    float l0 = 0.f, l1 = 0.f, l2 = 0.f, l3 = 0.f;
    {
        const char* gK = gKt + TBYTES;
        for (int kt = 0; kt < 32; kt++) {
            if (kt > 0) { CP_WAIT0(); __syncthreads(); }
            if (kt + 1 < 32) {
                unsigned d = dK[(kt + 1) & 1];
                #pragma unroll
                for (int it = 0; it < 4; it++)
                    cp_async16s(d + it * CH16, gK + it * 2048);
                CP_COMMIT();
                gK += TBYTES;
            }
            const unsigned ka = kA[kt & 1];

            uint64_t A0 = 0ull, A1 = 0ull, A2 = 0ull, A3 = 0ull;
            #pragma unroll
            for (int nt = 0; nt < 8; nt++) {
                float s0[4] = {0.f, 0.f, 0.f, 0.f};
                float s1[4] = {0.f, 0.f, 0.f, 0.f};
                #pragma unroll
                for (int kh = 0; kh < 2; kh++) {
                    uint32_t kb[4];
                    ldsm_x4(kb, ka + (unsigned)(nt * 8 * SQ * 2 + kh * 64));
                    mma16816(s0, qa[0][2*kh][0], qa[0][2*kh][1], qa[0][2*kh][2], qa[0][2*kh][3], kb[0], kb[1]);
                    mma16816(s0, qa[0][2*kh+1][0], qa[0][2*kh+1][1], qa[0][2*kh+1][2], qa[0][2*kh+1][3], kb[2], kb[3]);
                    mma16816(s1, qa[1][2*kh][0], qa[1][2*kh][1], qa[1][2*kh][2], qa[1][2*kh][3], kb[0], kb[1]);
                    mma16816(s1, qa[1][2*kh+1][0], qa[1][2*kh+1][1], qa[1][2*kh+1][2], qa[1][2*kh+1][3], kb[2], kb[3]);
                }
                // frag 0 -> rows qgrp, qgrp+8
                uint32_t u01 = pack_bf2(s0[0], s0[1]);
                uint32_t u23 = pack_bf2(s0[2], s0[3]);
                uint64_t ta = mul2(bfpair(u01), SCL2P);
                uint64_t tb = mul2(bfpair(u23), SCL2P);
                float x0, x1, y0, y1;
                up2(ta, x0, x1); up2(tb, y0, y1);
                A0 = add2(A0, pk2(ex2f(x0), ex2f(x1)));
                A1 = add2(A1, pk2(ex2f(y0), ex2f(y1)));
                // frag 1 -> rows qgrp+16, qgrp+24
                u01 = pack_bf2(s1[0], s1[1]);
                u23 = pack_bf2(s1[2], s1[3]);
                ta = mul2(bfpair(u01), SCL2P);
                tb = mul2(bfpair(u23), SCL2P);
                up2(ta, x0, x1); up2(tb, y0, y1);
                A2 = add2(A2, pk2(ex2f(x0), ex2f(x1)));
                A3 = add2(A3, pk2(ex2f(y0), ex2f(y1)));
            }
            float e0, e1;
            up2(A0, e0, e1); l0 += e0 + e1;
            up2(A1, e0, e1); l1 += e0 + e1;
            up2(A2, e0, e1); l2 += e0 + e1;
            up2(A3, e0, e1); l3 += e0 + e1;
        }
    }
    l0 += __shfl_xor_sync(0xffffffffu, l0, 1);
    l0 += __shfl_xor_sync(0xffffffffu, l0, 2);
    l1 += __shfl_xor_sync(0xffffffffu, l1, 1);
    l1 += __shfl_xor_sync(0xffffffffu, l1, 2);
    l2 += __shfl_xor_sync(0xffffffffu, l2, 1);
    l2 += __shfl_xor_sync(0xffffffffu, l2, 2);
    l3 += __shfl_xor_sync(0xffffffffu, l3, 1);
    l3 += __shfl_xor_sync(0xffffffffu, l3, 2);

    if ((lane & 3) == 0) {
        int qgrp = lane >> 2;
        int n0 = mblk * 128 + warp * 32 + qgrp;
        float* gl = g_l + (size_t)bh * Ndim;
        gl[n0]      = -__log2f(l0);
        gl[n0 + 8]  = -__log2f(l1);
        gl[n0 + 16] = -__log2f(l2);
        gl[n0 + 24] = -__log2f(l3);
    }
}

// ===================== PASS 2: P = bf16(2^(t-L)), O = P V (M=32 per warp) =====================
__global__ __launch_bounds__(128, 3) void pass2_kernel(float* __restrict__ out) {
    extern __shared__ __align__(16) __nv_bfloat16 smem[];
    __nv_bfloat16* sQ  = smem;
    __nv_bfloat16* sK0 = smem + QELEMS;
    __nv_bfloat16* sK1 = sK0 + TELEMS;
    __nv_bfloat16* sV0 = sK1 + TELEMS;
    __nv_bfloat16* sV1 = sV0 + TELEMS;

    const int tid  = threadIdx.x;
    const int warp = tid >> 5;
    const int lane = tid & 31;
    const int mblk = blockIdx.x;
    const int bh   = blockIdx.y;

    const __nv_bfloat16* Qg = g_q + (size_t)bh * Ndim * Ddim + (size_t)mblk * 128 * Ddim;
    const __nv_bfloat16* Kg = g_k + (size_t)bh * Ndim * Ddim;
    const __nv_bfloat16* Vg = g_v + (size_t)bh * Ndim * Ddim;

    const int krow = lane & 7;
    const int kc8  = (lane >> 3) & 3;
    const int vrow = lane & 15;
    const int vcsel = (lane & 16) ? 8 : 0;
    const unsigned kfragoff = (unsigned)((krow * SQ + kc8 * 8) * 2);
    const unsigned vfragoff = (unsigned)((vrow * SQ + vcsel) * 2);
    const unsigned kA[2] = { su(sK0) + kfragoff, su(sK1) + kfragoff };
    const unsigned vA[2] = { su(sV0) + vfragoff, su(sV1) + vfragoff };

    const int srow = tid >> 3, scol = tid & 7;
    const unsigned stoff = (unsigned)((srow * SQ + scol * 8) * 2);
    const unsigned dK[2] = { su(sK0) + stoff, su(sK1) + stoff };
    const unsigned dV[2] = { su(sV0) + stoff, su(sV1) + stoff };
    const char* gKt = (const char*)Kg + tid * 16;
    const char* gVt = (const char*)Vg + tid * 16;

    const int qgrp = lane >> 2;

    // row denominators
    const float* gl = g_l + (size_t)bh * Ndim + mblk * 128 + warp * 32 + qgrp;
    const uint64_t SCL2P = pk2(SCL2, SCL2);
    const uint64_t NLP[4] = { pk2(gl[0], gl[0]), pk2(gl[8], gl[8]),
                              pk2(gl[16], gl[16]), pk2(gl[24], gl[24]) };

    // stage Q + K0 + V0
    {
        const char* src = (const char*)Qg + tid * 16;
        unsigned qdst = su(sQ) + stoff;
        #pragma unroll
        for (int it = 0; it < 8; it++)
            cp_async16s(qdst + it * CH16, src + it * 2048);
        #pragma unroll
        for (int it = 0; it < 4; it++) {
            cp_async16s(dK[0] + it * CH16, gKt + it * 2048);
            cp_async16s(dV[0] + it * CH16, gVt + it * 2048);
        }
        CP_COMMIT();
        gKt += TBYTES; gVt += TBYTES;
    }
    CP_WAIT0();
    __syncthreads();

    uint32_t qa[2][4][4];
    #pragma unroll
    for (int f = 0; f < 2; f++) {
        int rofs = warp * 32 + f * 16 + (lane & 15);
        int cofs = (lane & 16) ? 8 : 0;
        unsigned qaddr = su(sQ) + (unsigned)((rofs * SQ + cofs) * 2);
        #pragma unroll
        for (int kk = 0; kk < 4; kk++)
            ldsm_x4(qa[f][kk], qaddr + kk * 32);
    }

    float oa[2][8][4];
    #pragma unroll
    for (int f = 0; f < 2; f++)
        #pragma unroll
        for (int u = 0; u < 8; u++)
            #pragma unroll
            for (int x = 0; x < 4; x++) oa[f][u][x] = 0.f;

    for (int kt = 0; kt < 32; kt++) {
        if (kt > 0) { CP_WAIT0(); __syncthreads(); }
        if (kt + 1 < 32) {
            unsigned dk = dK[(kt + 1) & 1];
            unsigned dv = dV[(kt + 1) & 1];
            #pragma unroll
            for (int it = 0; it < 4; it++) {
                cp_async16s(dk + it * CH16, gKt + it * 2048);
                cp_async16s(dv + it * CH16, gVt + it * 2048);
            }
            CP_COMMIT();
            gKt += TBYTES; gVt += TBYTES;
        }
        const unsigned ka = kA[kt & 1];
        const unsigned va = vA[kt & 1];

        // per 16-key group j: S (both frags) -> softmax -> PV (shared V frags)
        #pragma unroll
        for (int j = 0; j < 4; j++) {
            float sc[2][2][4];
            #pragma unroll
            for (int f = 0; f < 2; f++)
                #pragma unroll
                for (int t = 0; t < 2; t++)
                    #pragma unroll
                    for (int x = 0; x < 4; x++) sc[f][t][x] = 0.f;

            #pragma unroll
            for (int t = 0; t < 2; t++) {
                const int nt = 2 * j + t;
                #pragma unroll
                for (int kh = 0; kh < 2; kh++) {
                    uint32_t kb[4];
                    ldsm_x4(kb, ka + (unsigned)(nt * 8 * SQ * 2 + kh * 64));
                    mma16816(sc[0][t], qa[0][2*kh][0], qa[0][2*kh][1], qa[0][2*kh][2], qa[0][2*kh][3], kb[0], kb[1]);
                    mma16816(sc[0][t], qa[0][2*kh+1][0], qa[0][2*kh+1][1], qa[0][2*kh+1][2], qa[0][2*kh+1][3], kb[2], kb[3]);
                    mma16816(sc[1][t], qa[1][2*kh][0], qa[1][2*kh][1], qa[1][2*kh][2], qa[1][2*kh][3], kb[0], kb[1]);
                    mma16816(sc[1][t], qa[1][2*kh+1][0], qa[1][2*kh+1][1], qa[1][2*kh+1][2], qa[1][2*kh+1][3], kb[2], kb[3]);
                }
            }

            uint32_t Af[2][4];
            #pragma unroll
            for (int f = 0; f < 2; f++) {
                #pragma unroll
                for (int t = 0; t < 2; t++) {
                    uint32_t u01 = pack_bf2(sc[f][t][0], sc[f][t][1]);
                    uint32_t u23 = pack_bf2(sc[f][t][2], sc[f][t][3]);
                    uint64_t ta = fma2(bfpair(u01), SCL2P, NLP[2*f]);
                    uint64_t tb = fma2(bfpair(u23), SCL2P, NLP[2*f + 1]);
                    float x0, x1, y0, y1;
                    up2(ta, x0, x1);
                    up2(tb, y0, y1);
                    Af[f][2*t]     = pack_bf2(ex2f(x0), ex2f(x1));
                    Af[f][2*t + 1] = pack_bf2(ex2f(y0), ex2f(y1));
                }
            }

            #pragma unroll
            for (int up = 0; up < 4; up++) {
                uint32_t vb[4];
                ldsm_x4_t(vb, va + (unsigned)(j * 16 * SQ * 2 + up * 32));
                mma16816(oa[0][2*up],     Af[0][0], Af[0][1], Af[0][2], Af[0][3], vb[0], vb[1]);
                mma16816(oa[0][2*up + 1], Af[0][0], Af[0][1], Af[0][2], Af[0][3], vb[2], vb[3]);
                mma16816(oa[1][2*up],     Af[1][0], Af[1][1], Af[1][2], Af[1][3], vb[0], vb[1]);
                mma16816(oa[1][2*up + 1], Af[1][0], Af[1][1], Af[1][2], Af[1][3], vb[2], vb[3]);
            }
        }
    }

    // epilogue: bf16-round O, store as float32 in [B,N,H*D]
    int b = bh >> 4, h = bh & 15;
    const int tq = lane & 3;
    #pragma unroll
    for (int f = 0; f < 2; f++) {
        int n0 = mblk * 128 + warp * 32 + f * 16 + qgrp;
        size_t base0 = ((size_t)b * Ndim + n0) * (Hdim * Ddim) + (size_t)h * Ddim;
        size_t base1 = base0 + (size_t)8 * (Hdim * Ddim);
        #pragma unroll
        for (int u = 0; u < 8; u++) {
            int d = u * 8 + 2 * tq;
            float2 w0 = { rb(oa[f][u][0]), rb(oa[f][u][1]) };
            float2 w1 = { rb(oa[f][u][2]), rb(oa[f][u][3]) };
            *(float2*)(out + base0 + d) = w0;
            *(float2*)(out + base1 + d) = w1;
        }
    }
}

// ---------------- launch ----------------
extern "C" void kernel_launch(void* const* d_in, const int* in_sizes, int n_in,
                              void* d_out, int out_size) {
    (void)in_sizes; (void)n_in; (void)out_size;
    const float* q = (const float*)d_in[0];
    const float* k = (const float*)d_in[1];
    const float* v = (const float*)d_in[2];
    float* out = (float*)d_out;

    cudaFuncSetAttribute(pass1_kernel, cudaFuncAttributeMaxDynamicSharedMemorySize, SMEMB1);
    cudaFuncSetAttribute(pass2_kernel, cudaFuncAttributeMaxDynamicSharedMemorySize, SMEMB2);

    cvt_kernel<<<TOTE / 1024, 256>>>(q, k, v);

    dim3 grid(Ndim / 128, Bdim * Hdim);
    pass1_kernel<<<grid, 128, SMEMB1>>>();
    pass2_kernel<<<grid, 128, SMEMB2>>>(out);
}

// round 16
// speedup vs baseline: 1.1833x; 1.1833x over previous
#include <cuda_runtime.h>
#include <cuda_bf16.h>
#include <cstdint>

#define Bdim 4
#define Hdim 16
#define Ndim 2048
#define Ddim 64
#define TOTE (Bdim*Hdim*Ndim*Ddim)   // 8388608
#define BHN  (Bdim*Hdim*Ndim)        // 131072

// bf16 scratch in [B, H, N, D] layout
__device__ __align__(16) __nv_bfloat16 g_q[TOTE];
__device__ __align__(16) __nv_bfloat16 g_k[TOTE];
__device__ __align__(16) __nv_bfloat16 g_v[TOTE];
// raw partial denominators, one buffer per K-half: [half][bh][n]
__device__ __align__(16) float g_l2[2 * BHN];

// ---------------- converter: [B,N,H*D] f32 -> [B,H,N,D] bf16 ----------------
__global__ void cvt_kernel(const float* __restrict__ q,
                           const float* __restrict__ k,
                           const float* __restrict__ v) {
    long i4 = (long)blockIdx.x * blockDim.x + threadIdx.x;
    long o = i4 * 4;
    if (o >= TOTE) return;
    int d = (int)(o & 63);
    int n = (int)((o >> 6) & 2047);
    int h = (int)((o >> 17) & 15);
    int b = (int)(o >> 21);
    long in_off = (((long)b * Ndim + n) * Hdim + h) * Ddim + d;

    float4 fq = *(const float4*)(q + in_off);
    float4 fk = *(const float4*)(k + in_off);
    float4 fv = *(const float4*)(v + in_off);

    __nv_bfloat162 q0 = __floats2bfloat162_rn(fq.x, fq.y);
    __nv_bfloat162 q1 = __floats2bfloat162_rn(fq.z, fq.w);
    __nv_bfloat162 k0 = __floats2bfloat162_rn(fk.x, fk.y);
    __nv_bfloat162 k1 = __floats2bfloat162_rn(fk.z, fk.w);
    __nv_bfloat162 v0 = __floats2bfloat162_rn(fv.x, fv.y);
    __nv_bfloat162 v1 = __floats2bfloat162_rn(fv.z, fv.w);

    uint2 uq = { *(uint32_t*)&q0, *(uint32_t*)&q1 };
    uint2 uk = { *(uint32_t*)&k0, *(uint32_t*)&k1 };
    uint2 uv = { *(uint32_t*)&v0, *(uint32_t*)&v1 };
    *(uint2*)(g_q + o) = uq;
    *(uint2*)(g_k + o) = uk;
    *(uint2*)(g_v + o) = uv;
}

// ---------------- helpers ----------------
__device__ __forceinline__ unsigned su(const void* p) {
    return (unsigned)__cvta_generic_to_shared(p);
}
__device__ __forceinline__ void ldsm_x4(uint32_t r[4], unsigned addr) {
    asm volatile("ldmatrix.sync.aligned.m8n8.x4.shared.b16 {%0,%1,%2,%3}, [%4];"
                 : "=r"(r[0]), "=r"(r[1]), "=r"(r[2]), "=r"(r[3]) : "r"(addr));
}
__device__ __forceinline__ void ldsm_x4_t(uint32_t r[4], unsigned addr) {
    asm volatile("ldmatrix.sync.aligned.m8n8.x4.trans.shared.b16 {%0,%1,%2,%3}, [%4];"
                 : "=r"(r[0]), "=r"(r[1]), "=r"(r[2]), "=r"(r[3]) : "r"(addr));
}
__device__ __forceinline__ void mma16816(float c[4],
                                         uint32_t a0, uint32_t a1, uint32_t a2, uint32_t a3,
                                         uint32_t b0, uint32_t b1) {
    asm volatile(
        "mma.sync.aligned.m16n8k16.row.col.f32.bf16.bf16.f32 "
        "{%0,%1,%2,%3}, {%4,%5,%6,%7}, {%8,%9}, {%0,%1,%2,%3};"
        : "+f"(c[0]), "+f"(c[1]), "+f"(c[2]), "+f"(c[3])
        : "r"(a0), "r"(a1), "r"(a2), "r"(a3), "r"(b0), "r"(b1));
}
__device__ __forceinline__ float ex2f(float x) {
    float y; asm("ex2.approx.f32 %0, %1;" : "=f"(y) : "f"(x)); return y;
}
__device__ __forceinline__ uint32_t pack_bf2(float a, float b) {
    __nv_bfloat162 t = __floats2bfloat162_rn(a, b);
    return *reinterpret_cast<uint32_t*>(&t);
}
__device__ __forceinline__ float rb(float x) {
    return __bfloat162float(__float2bfloat16(x));
}
// packed f32x2 ops (FFMA2-class, fma pipe, 2 lanes per issue)
__device__ __forceinline__ uint64_t bfpair(uint32_t u) {   // bf16x2 word -> f32 pair
    uint64_t p;
    asm("{\n\t.reg .b32 lo, hi;\n\t"
        "shl.b32 lo, %1, 16;\n\t"
        "and.b32 hi, %1, 0xFFFF0000;\n\t"
        "mov.b64 %0, {lo, hi};\n\t}"
        : "=l"(p) : "r"(u));
    return p;
}
__device__ __forceinline__ uint64_t pk2(float x, float y) {
    uint64_t p; asm("mov.b64 %0, {%1, %2};" : "=l"(p) : "f"(x), "f"(y)); return p;
}
__device__ __forceinline__ void up2(uint64_t p, float& x, float& y) {
    asm("mov.b64 {%0, %1}, %2;" : "=f"(x), "=f"(y) : "l"(p));
}
__device__ __forceinline__ uint64_t mul2(uint64_t a, uint64_t b) {
    uint64_t r; asm("mul.rn.f32x2 %0, %1, %2;" : "=l"(r) : "l"(a), "l"(b)); return r;
}
__device__ __forceinline__ uint64_t fma2(uint64_t a, uint64_t b, uint64_t c) {
    uint64_t r; asm("fma.rn.f32x2 %0, %1, %2, %3;" : "=l"(r) : "l"(a), "l"(b), "l"(c)); return r;
}
__device__ __forceinline__ uint64_t add2(uint64_t a, uint64_t b) {
    uint64_t r; asm("add.rn.f32x2 %0, %1, %2;" : "=l"(r) : "l"(a), "l"(b)); return r;
}
__device__ __forceinline__ void cp_async16s(unsigned smem, const void* gmem) {
    asm volatile("cp.async.cg.shared.global [%0], [%1], 16;\n"
                 :: "r"(smem), "l"(gmem));
}
#define CP_COMMIT() asm volatile("cp.async.commit_group;\n" ::: "memory")
#define CP_WAIT0()  asm volatile("cp.async.wait_group 0;\n" ::: "memory")

constexpr int SQ = 72;    // smem row stride (bf16); conflict-free for ldsm pattern
constexpr int QELEMS = 128 * SQ;
constexpr int TELEMS = 64 * SQ;
constexpr int SMEMB1 = (QELEMS + 2 * TELEMS) * 2;   // pass1: Q + 2 K bufs = 36864
constexpr int SMEMB2 = (QELEMS + 4 * TELEMS) * 2;   // pass2: Q + 2K + 2V = 55296
constexpr int TBYTES = 64 * Ddim * 2;               // 8192
constexpr int HTILES = 16;                          // K tiles per pass1 half

// scale * log2(e)
#define SCL2 0.18033688011112042f

// ===================== PASS 1 kernel: partial denominators (half-K split) =====================
__global__ __launch_bounds__(256, 3) void pass1_kernel() {
    extern __shared__ __align__(16) __nv_bfloat16 smem[];
    __nv_bfloat16* sQ  = smem;
    __nv_bfloat16* sK0 = smem + QELEMS;
    __nv_bfloat16* sK1 = sK0 + TELEMS;

    const int tid  = threadIdx.x;
    const int warp = tid >> 5;
    const int lane = tid & 31;
    const int mblk = blockIdx.x;
    const int bh   = blockIdx.y;
    const int half = blockIdx.z;   // 0 or 1: which 1024-key half

    const __nv_bfloat16* Qg = g_q + (size_t)bh * Ndim * Ddim + (size_t)mblk * 128 * Ddim;
    const __nv_bfloat16* Kg = g_k + (size_t)bh * Ndim * Ddim + (size_t)half * HTILES * 64 * Ddim;

    const int krow = lane & 7;
    const int kc8  = (lane >> 3) & 3;
    const unsigned kfragoff = (unsigned)((krow * SQ + kc8 * 8) * 2);
    const unsigned kA[2] = { su(sK0) + kfragoff, su(sK1) + kfragoff };

    const int srow = tid >> 3, scol = tid & 7;
    const unsigned stoff0 = (unsigned)((srow * SQ + scol * 8) * 2);
    const unsigned stoff1 = stoff0 + (unsigned)(32 * SQ * 2);
    const unsigned dKs[2][2] = { { su(sK0) + stoff0, su(sK0) + stoff1 },
                                 { su(sK1) + stoff0, su(sK1) + stoff1 } };
    const char* gKt = (const char*)Kg + tid * 16;

    const uint64_t SCL2P = pk2(SCL2, SCL2);

    // stage Q + K0
    {
        const char* src = (const char*)Qg;
        unsigned qdst = su(sQ) + stoff0;
        #pragma unroll
        for (int it = 0; it < 4; it++)
            cp_async16s(qdst + it * (unsigned)(32 * SQ * 2), src + tid * 16 + it * 4096);
        cp_async16s(dKs[0][0], gKt);
        cp_async16s(dKs[0][1], gKt + 4096);
        CP_COMMIT();
    }
    CP_WAIT0();
    __syncthreads();

    uint32_t qa[4][4];
    {
        int rofs = warp * 16 + (lane & 15);
        int cofs = (lane & 16) ? 8 : 0;
        unsigned qaddr = su(sQ) + (unsigned)((rofs * SQ + cofs) * 2);
        #pragma unroll
        for (int kk = 0; kk < 4; kk++)
            ldsm_x4(qa[kk], qaddr + kk * 32);
    }

    float l0 = 0.f, l1 = 0.f;
    {
        const char* gK = gKt + TBYTES;
        for (int kt = 0; kt < HTILES; kt++) {
            if (kt > 0) { CP_WAIT0(); __syncthreads(); }
            if (kt + 1 < HTILES) {
                const unsigned* d = dKs[(kt + 1) & 1];
                cp_async16s(d[0], gK);
                cp_async16s(d[1], gK + 4096);
                CP_COMMIT();
                gK += TBYTES;
            }
            const unsigned ka = kA[kt & 1];

            float sc[8][4];
            #pragma unroll
            for (int nt = 0; nt < 8; nt++)
                #pragma unroll
                for (int x = 0; x < 4; x++) sc[nt][x] = 0.f;

            #pragma unroll
            for (int nt = 0; nt < 8; nt++) {
                #pragma unroll
                for (int kh = 0; kh < 2; kh++) {
                    uint32_t kb[4];
                    ldsm_x4(kb, ka + (unsigned)(nt * 8 * SQ * 2 + kh * 64));
                    mma16816(sc[nt], qa[2*kh][0], qa[2*kh][1], qa[2*kh][2], qa[2*kh][3], kb[0], kb[1]);
                    mma16816(sc[nt], qa[2*kh+1][0], qa[2*kh+1][1], qa[2*kh+1][2], qa[2*kh+1][3], kb[2], kb[3]);
                }
            }
            // exp-sum of the EXACT bf16-rounded scores, packed f32x2 accumulation
            uint64_t A0 = 0ull, A1 = 0ull;
            #pragma unroll
            for (int nt = 0; nt < 8; nt++) {
                uint32_t u01 = pack_bf2(sc[nt][0], sc[nt][1]);
                uint32_t u23 = pack_bf2(sc[nt][2], sc[nt][3]);
                uint64_t ta = mul2(bfpair(u01), SCL2P);
                uint64_t tb = mul2(bfpair(u23), SCL2P);
                float x0, x1, y0, y1;
                up2(ta, x0, x1);
                up2(tb, y0, y1);
                A0 = add2(A0, pk2(ex2f(x0), ex2f(x1)));
                A1 = add2(A1, pk2(ex2f(y0), ex2f(y1)));
            }
            float e0, e1, f0, f1;
            up2(A0, e0, e1);
            up2(A1, f0, f1);
            l0 += e0 + e1;
            l1 += f0 + f1;
        }
    }
    l0 += __shfl_xor_sync(0xffffffffu, l0, 1);
    l0 += __shfl_xor_sync(0xffffffffu, l0, 2);
    l1 += __shfl_xor_sync(0xffffffffu, l1, 1);
    l1 += __shfl_xor_sync(0xffffffffu, l1, 2);

    if ((lane & 3) == 0) {
        int qgrp = lane >> 2;
        int n0 = mblk * 128 + warp * 16 + qgrp;
        float* gl = g_l2 + (size_t)half * BHN + (size_t)bh * Ndim;
        gl[n0]     = l0;     // raw partial sum
        gl[n0 + 8] = l1;
    }
}

// ===================== PASS 2 kernel: P = bf16(2^(t-L)), O = P V =====================
__global__ __launch_bounds__(256, 2) void pass2_kernel(float* __restrict__ out) {
    extern __shared__ __align__(16) __nv_bfloat16 smem[];
    __nv_bfloat16* sQ  = smem;
    __nv_bfloat16* sK0 = smem + QELEMS;
    __nv_bfloat16* sK1 = sK0 + TELEMS;
    __nv_bfloat16* sV0 = sK1 + TELEMS;
    __nv_bfloat16* sV1 = sV0 + TELEMS;

    const int tid  = threadIdx.x;
    const int warp = tid >> 5;
    const int lane = tid & 31;
    const int mblk = blockIdx.x;
    const int bh   = blockIdx.y;

    const __nv_bfloat16* Qg = g_q + (size_t)bh * Ndim * Ddim + (size_t)mblk * 128 * Ddim;
    const __nv_bfloat16* Kg = g_k + (size_t)bh * Ndim * Ddim;
    const __nv_bfloat16* Vg = g_v + (size_t)bh * Ndim * Ddim;

    const int krow = lane & 7;
    const int kc8  = (lane >> 3) & 3;
    const int vrow = lane & 15;
    const int vcsel = (lane & 16) ? 8 : 0;
    const unsigned kfragoff = (unsigned)((krow * SQ + kc8 * 8) * 2);
    const unsigned vfragoff = (unsigned)((vrow * SQ + vcsel) * 2);
    const unsigned kA[2] = { su(sK0) + kfragoff, su(sK1) + kfragoff };
    const unsigned vA[2] = { su(sV0) + vfragoff, su(sV1) + vfragoff };

    const int srow = tid >> 3, scol = tid & 7;
    const unsigned stoff0 = (unsigned)((srow * SQ + scol * 8) * 2);
    const unsigned stoff1 = stoff0 + (unsigned)(32 * SQ * 2);
    const unsigned dKs[2][2] = { { su(sK0) + stoff0, su(sK0) + stoff1 },
                                 { su(sK1) + stoff0, su(sK1) + stoff1 } };
    const unsigned dVs[2][2] = { { su(sV0) + stoff0, su(sV0) + stoff1 },
                                 { su(sV1) + stoff0, su(sV1) + stoff1 } };
    const char* gKt = (const char*)Kg + tid * 16;
    const char* gVt = (const char*)Vg + tid * 16;

    const int qgrp = lane >> 2;

    // row denominators: sum the two half-K partials (fixed order -> deterministic)
    const size_t lidx = (size_t)bh * Ndim + mblk * 128 + warp * 16 + qgrp;
    const float nL0 = -__log2f(g_l2[lidx] + g_l2[BHN + lidx]);
    const float nL1 = -__log2f(g_l2[lidx + 8] + g_l2[BHN + lidx + 8]);
    const uint64_t SCL2P = pk2(SCL2, SCL2);
    const uint64_t NL0P  = pk2(nL0, nL0);
    const uint64_t NL1P  = pk2(nL1, nL1);

    // stage Q + K0 + V0
    {
        const char* src = (const char*)Qg;
        unsigned qdst = su(sQ) + stoff0;
        #pragma unroll
        for (int it = 0; it < 4; it++)
            cp_async16s(qdst + it * (unsigned)(32 * SQ * 2), src + tid * 16 + it * 4096);
        cp_async16s(dKs[0][0], gKt);
        cp_async16s(dKs[0][1], gKt + 4096);
        cp_async16s(dVs[0][0], gVt);
        cp_async16s(dVs[0][1], gVt + 4096);
        CP_COMMIT();
        gKt += TBYTES; gVt += TBYTES;
    }
    CP_WAIT0();
    __syncthreads();

    uint32_t qa[4][4];
    {
        int rofs = warp * 16 + (lane & 15);
        int cofs = (lane & 16) ? 8 : 0;
        unsigned qaddr = su(sQ) + (unsigned)((rofs * SQ + cofs) * 2);
        #pragma unroll
        for (int kk = 0; kk < 4; kk++)
            ldsm_x4(qa[kk], qaddr + kk * 32);
    }

    float oa[8][4];
    #pragma unroll
    for (int u = 0; u < 8; u++)
        #pragma unroll
        for (int x = 0; x < 4; x++) oa[u][x] = 0.f;

    for (int kt = 0; kt < 32; kt++) {
        if (kt > 0) { CP_WAIT0(); __syncthreads(); }
        if (kt + 1 < 32) {
            const unsigned* dK = dKs[(kt + 1) & 1];
            const unsigned* dV = dVs[(kt + 1) & 1];
            cp_async16s(dK[0], gKt);
            cp_async16s(dK[1], gKt + 4096);
            cp_async16s(dV[0], gVt);
            cp_async16s(dV[1], gVt + 4096);
            CP_COMMIT();
            gKt += TBYTES; gVt += TBYTES;
        }
        const unsigned ka = kA[kt & 1];
        const unsigned va = vA[kt & 1];

        float sc[8][4];
        #pragma unroll
        for (int nt = 0; nt < 8; nt++)
            #pragma unroll
            for (int x = 0; x < 4; x++) sc[nt][x] = 0.f;

        #pragma unroll
        for (int nt = 0; nt < 8; nt++) {
            #pragma unroll
            for (int kh = 0; kh < 2; kh++) {
                uint32_t kb[4];
                ldsm_x4(kb, ka + (unsigned)(nt * 8 * SQ * 2 + kh * 64));
                mma16816(sc[nt], qa[2*kh][0], qa[2*kh][1], qa[2*kh][2], qa[2*kh][3], kb[0], kb[1]);
                mma16816(sc[nt], qa[2*kh+1][0], qa[2*kh+1][1], qa[2*kh+1][2], qa[2*kh+1][3], kb[2], kb[3]);
            }
        }

        uint32_t pA[8][2];
        #pragma unroll
        for (int nt = 0; nt < 8; nt++) {
            uint32_t u01 = pack_bf2(sc[nt][0], sc[nt][1]);
            uint32_t u23 = pack_bf2(sc[nt][2], sc[nt][3]);
            uint64_t ta = fma2(bfpair(u01), SCL2P, NL0P);
            uint64_t tb = fma2(bfpair(u23), SCL2P, NL1P);
            float x0, x1, y0, y1;
            up2(ta, x0, x1);
            up2(tb, y0, y1);
            pA[nt][0] = pack_bf2(ex2f(x0), ex2f(x1));
            pA[nt][1] = pack_bf2(ex2f(y0), ex2f(y1));
        }

        #pragma unroll
        for (int j = 0; j < 4; j++) {
            uint32_t A0 = pA[2*j][0], A1 = pA[2*j][1];
            uint32_t A2 = pA[2*j+1][0], A3 = pA[2*j+1][1];
            #pragma unroll
            for (int up = 0; up < 4; up++) {
                uint32_t vb[4];
                ldsm_x4_t(vb, va + (unsigned)(j * 16 * SQ * 2 + up * 32));
                mma16816(oa[2*up],     A0, A1, A2, A3, vb[0], vb[1]);
                mma16816(oa[2*up + 1], A0, A1, A2, A3, vb[2], vb[3]);
            }
        }
    }

    // epilogue: bf16-round O, store as float32 in [B,N,H*D]
    int b = bh >> 4, h = bh & 15;
    int n0 = mblk * 128 + warp * 16 + qgrp;
    size_t base0 = ((size_t)b * Ndim + n0) * (Hdim * Ddim) + (size_t)h * Ddim;
    size_t base1 = base0 + (size_t)8 * (Hdim * Ddim);
    const int tq = lane & 3;
    #pragma unroll
    for (int u = 0; u < 8; u++) {
        int d = u * 8 + 2 * tq;
        float2 w0 = { rb(oa[u][0]), rb(oa[u][1]) };
        float2 w1 = { rb(oa[u][2]), rb(oa[u][3]) };
        *(float2*)(out + base0 + d) = w0;
        *(float2*)(out + base1 + d) = w1;
    }
}

// ---------------- launch ----------------
extern "C" void kernel_launch(void* const* d_in, const int* in_sizes, int n_in,
                              void* d_out, int out_size) {
    (void)in_sizes; (void)n_in; (void)out_size;
    const float* q = (const float*)d_in[0];
    const float* k = (const float*)d_in[1];
    const float* v = (const float*)d_in[2];
    float* out = (float*)d_out;

    cudaFuncSetAttribute(pass1_kernel, cudaFuncAttributeMaxDynamicSharedMemorySize, SMEMB1);
    cudaFuncSetAttribute(pass2_kernel, cudaFuncAttributeMaxDynamicSharedMemorySize, SMEMB2);

    cvt_kernel<<<TOTE / 1024, 256>>>(q, k, v);

    dim3 grid1(Ndim / 128, Bdim * Hdim, 2);
    pass1_kernel<<<grid1, 256, SMEMB1>>>();
    dim3 grid2(Ndim / 128, Bdim * Hdim);
    pass2_kernel<<<grid2, 256, SMEMB2>>>(out);
}

// round 17
// speedup vs baseline: 1.2241x; 1.0345x over previous
#include <cuda_runtime.h>
#include <cuda_bf16.h>
#include <cstdint>

#define Bdim 4
#define Hdim 16
#define Ndim 2048
#define Ddim 64
#define TOTE (Bdim*Hdim*Ndim*Ddim)   // 8388608
#define BHN  (Bdim*Hdim*Ndim)        // 131072

// bf16 scratch in [B, H, N, D] layout
__device__ __align__(16) __nv_bfloat16 g_q[TOTE];
__device__ __align__(16) __nv_bfloat16 g_k[TOTE];
__device__ __align__(16) __nv_bfloat16 g_v[TOTE];
// raw partial denominators, one buffer per K-half: [half][bh][n]
__device__ __align__(16) float g_l2[2 * BHN];

// ---------------- converter: [B,N,H*D] f32 -> [B,H,N,D] bf16 ----------------
__global__ void cvt_kernel(const float* __restrict__ q,
                           const float* __restrict__ k,
                           const float* __restrict__ v) {
    long i4 = (long)blockIdx.x * blockDim.x + threadIdx.x;
    long o = i4 * 4;
    if (o >= TOTE) return;
    int d = (int)(o & 63);
    int n = (int)((o >> 6) & 2047);
    int h = (int)((o >> 17) & 15);
    int b = (int)(o >> 21);
    long in_off = (((long)b * Ndim + n) * Hdim + h) * Ddim + d;

    float4 fq = *(const float4*)(q + in_off);
    float4 fk = *(const float4*)(k + in_off);
    float4 fv = *(const float4*)(v + in_off);

    __nv_bfloat162 q0 = __floats2bfloat162_rn(fq.x, fq.y);
    __nv_bfloat162 q1 = __floats2bfloat162_rn(fq.z, fq.w);
    __nv_bfloat162 k0 = __floats2bfloat162_rn(fk.x, fk.y);
    __nv_bfloat162 k1 = __floats2bfloat162_rn(fk.z, fk.w);
    __nv_bfloat162 v0 = __floats2bfloat162_rn(fv.x, fv.y);
    __nv_bfloat162 v1 = __floats2bfloat162_rn(fv.z, fv.w);

    uint2 uq = { *(uint32_t*)&q0, *(uint32_t*)&q1 };
    uint2 uk = { *(uint32_t*)&k0, *(uint32_t*)&k1 };
    uint2 uv = { *(uint32_t*)&v0, *(uint32_t*)&v1 };
    *(uint2*)(g_q + o) = uq;
    *(uint2*)(g_k + o) = uk;
    *(uint2*)(g_v + o) = uv;
}

// ---------------- helpers ----------------
__device__ __forceinline__ unsigned su(const void* p) {
    return (unsigned)__cvta_generic_to_shared(p);
}
__device__ __forceinline__ void ldsm_x4(uint32_t r[4], unsigned addr) {
    asm volatile("ldmatrix.sync.aligned.m8n8.x4.shared.b16 {%0,%1,%2,%3}, [%4];"
                 : "=r"(r[0]), "=r"(r[1]), "=r"(r[2]), "=r"(r[3]) : "r"(addr));
}
__device__ __forceinline__ void ldsm_x4_t(uint32_t r[4], unsigned addr) {
    asm volatile("ldmatrix.sync.aligned.m8n8.x4.trans.shared.b16 {%0,%1,%2,%3}, [%4];"
                 : "=r"(r[0]), "=r"(r[1]), "=r"(r[2]), "=r"(r[3]) : "r"(addr));
}
__device__ __forceinline__ void mma16816(float c[4],
                                         uint32_t a0, uint32_t a1, uint32_t a2, uint32_t a3,
                                         uint32_t b0, uint32_t b1) {
    asm volatile(
        "mma.sync.aligned.m16n8k16.row.col.f32.bf16.bf16.f32 "
        "{%0,%1,%2,%3}, {%4,%5,%6,%7}, {%8,%9}, {%0,%1,%2,%3};"
        : "+f"(c[0]), "+f"(c[1]), "+f"(c[2]), "+f"(c[3])
        : "r"(a0), "r"(a1), "r"(a2), "r"(a3), "r"(b0), "r"(b1));
}
__device__ __forceinline__ float ex2f(float x) {
    float y; asm("ex2.approx.f32 %0, %1;" : "=f"(y) : "f"(x)); return y;
}
__device__ __forceinline__ uint32_t pack_bf2(float a, float b) {
    __nv_bfloat162 t = __floats2bfloat162_rn(a, b);
    return *reinterpret_cast<uint32_t*>(&t);
}
__device__ __forceinline__ float rb(float x) {
    return __bfloat162float(__float2bfloat16(x));
}
// packed f32x2 ops (FFMA2-class, fma pipe, 2 lanes per issue)
__device__ __forceinline__ uint64_t bfpair(uint32_t u) {   // bf16x2 word -> f32 pair
    uint64_t p;
    asm("{\n\t.reg .b32 lo, hi;\n\t"
        "shl.b32 lo, %1, 16;\n\t"
        "and.b32 hi, %1, 0xFFFF0000;\n\t"
        "mov.b64 %0, {lo, hi};\n\t}"
        : "=l"(p) : "r"(u));
    return p;
}
__device__ __forceinline__ uint64_t pk2(float x, float y) {
    uint64_t p; asm("mov.b64 %0, {%1, %2};" : "=l"(p) : "f"(x), "f"(y)); return p;
}
__device__ __forceinline__ void up2(uint64_t p, float& x, float& y) {
    asm("mov.b64 {%0, %1}, %2;" : "=f"(x), "=f"(y) : "l"(p));
}
__device__ __forceinline__ uint64_t mul2(uint64_t a, uint64_t b) {
    uint64_t r; asm("mul.rn.f32x2 %0, %1, %2;" : "=l"(r) : "l"(a), "l"(b)); return r;
}
__device__ __forceinline__ uint64_t fma2(uint64_t a, uint64_t b, uint64_t c) {
    uint64_t r; asm("fma.rn.f32x2 %0, %1, %2, %3;" : "=l"(r) : "l"(a), "l"(b), "l"(c)); return r;
}
__device__ __forceinline__ uint64_t add2(uint64_t a, uint64_t b) {
    uint64_t r; asm("add.rn.f32x2 %0, %1, %2;" : "=l"(r) : "l"(a), "l"(b)); return r;
}
__device__ __forceinline__ void cp_async16s(unsigned smem, const void* gmem) {
    asm volatile("cp.async.cg.shared.global [%0], [%1], 16;\n"
                 :: "r"(smem), "l"(gmem));
}
#define CP_COMMIT() asm volatile("cp.async.commit_group;\n" ::: "memory")
#define CP_WAIT0()  asm volatile("cp.async.wait_group 0;\n" ::: "memory")

constexpr int SQ = 72;    // smem row stride (bf16); conflict-free for ldsm pattern
constexpr int QELEMS = 128 * SQ;
constexpr int TELEMS = 64 * SQ;
constexpr int SMEMB1 = (QELEMS + 2 * TELEMS) * 2;   // pass1: Q + 2 K bufs = 36864
constexpr int SMEMB2 = (QELEMS + 4 * TELEMS) * 2;   // pass2: Q + 2K + 2V = 55296
constexpr int TBYTES = 64 * Ddim * 2;               // 8192
constexpr int HTILES = 16;                          // K tiles per pass1 half

// scale * log2(e)
#define SCL2 0.18033688011112042f

// ===================== PASS 1 kernel: partial denominators (half-K split) =====================
__global__ __launch_bounds__(256, 3) void pass1_kernel(int bhbase) {
    extern __shared__ __align__(16) __nv_bfloat16 smem[];
    __nv_bfloat16* sQ  = smem;
    __nv_bfloat16* sK0 = smem + QELEMS;
    __nv_bfloat16* sK1 = sK0 + TELEMS;

    const int tid  = threadIdx.x;
    const int warp = tid >> 5;
    const int lane = tid & 31;
    const int mblk = blockIdx.x;
    const int bh   = blockIdx.y + bhbase;
    const int half = blockIdx.z;   // 0 or 1: which 1024-key half

    const __nv_bfloat16* Qg = g_q + (size_t)bh * Ndim * Ddim + (size_t)mblk * 128 * Ddim;
    const __nv_bfloat16* Kg = g_k + (size_t)bh * Ndim * Ddim + (size_t)half * HTILES * 64 * Ddim;

    const int krow = lane & 7;
    const int kc8  = (lane >> 3) & 3;
    const unsigned kfragoff = (unsigned)((krow * SQ + kc8 * 8) * 2);
    const unsigned kA[2] = { su(sK0) + kfragoff, su(sK1) + kfragoff };

    const int srow = tid >> 3, scol = tid & 7;
    const unsigned stoff0 = (unsigned)((srow * SQ + scol * 8) * 2);
    const unsigned stoff1 = stoff0 + (unsigned)(32 * SQ * 2);
    const unsigned dKs[2][2] = { { su(sK0) + stoff0, su(sK0) + stoff1 },
                                 { su(sK1) + stoff0, su(sK1) + stoff1 } };
    const char* gKt = (const char*)Kg + tid * 16;

    const uint64_t SCL2P = pk2(SCL2, SCL2);

    // stage Q + K0
    {
        const char* src = (const char*)Qg;
        unsigned qdst = su(sQ) + stoff0;
        #pragma unroll
        for (int it = 0; it < 4; it++)
            cp_async16s(qdst + it * (unsigned)(32 * SQ * 2), src + tid * 16 + it * 4096);
        cp_async16s(dKs[0][0], gKt);
        cp_async16s(dKs[0][1], gKt + 4096);
        CP_COMMIT();
    }
    CP_WAIT0();
    __syncthreads();

    uint32_t qa[4][4];
    {
        int rofs = warp * 16 + (lane & 15);
        int cofs = (lane & 16) ? 8 : 0;
        unsigned qaddr = su(sQ) + (unsigned)((rofs * SQ + cofs) * 2);
        #pragma unroll
        for (int kk = 0; kk < 4; kk++)
            ldsm_x4(qa[kk], qaddr + kk * 32);
    }

    float l0 = 0.f, l1 = 0.f;
    {
        const char* gK = gKt + TBYTES;
        for (int kt = 0; kt < HTILES; kt++) {
            if (kt > 0) { CP_WAIT0(); __syncthreads(); }
            if (kt + 1 < HTILES) {
                const unsigned* d = dKs[(kt + 1) & 1];
                cp_async16s(d[0], gK);
                cp_async16s(d[1], gK + 4096);
                CP_COMMIT();
                gK += TBYTES;
            }
            const unsigned ka = kA[kt & 1];

            float sc[8][4];
            #pragma unroll
            for (int nt = 0; nt < 8; nt++)
                #pragma unroll
                for (int x = 0; x < 4; x++) sc[nt][x] = 0.f;

            #pragma unroll
            for (int nt = 0; nt < 8; nt++) {
                #pragma unroll
                for (int kh = 0; kh < 2; kh++) {
                    uint32_t kb[4];
                    ldsm_x4(kb, ka + (unsigned)(nt * 8 * SQ * 2 + kh * 64));
                    mma16816(sc[nt], qa[2*kh][0], qa[2*kh][1], qa[2*kh][2], qa[2*kh][3], kb[0], kb[1]);
                    mma16816(sc[nt], qa[2*kh+1][0], qa[2*kh+1][1], qa[2*kh+1][2], qa[2*kh+1][3], kb[2], kb[3]);
                }
            }
            // exp-sum of the EXACT bf16-rounded scores, packed f32x2 accumulation
            uint64_t A0 = 0ull, A1 = 0ull;
            #pragma unroll
            for (int nt = 0; nt < 8; nt++) {
                uint32_t u01 = pack_bf2(sc[nt][0], sc[nt][1]);
                uint32_t u23 = pack_bf2(sc[nt][2], sc[nt][3]);
                uint64_t ta = mul2(bfpair(u01), SCL2P);
                uint64_t tb = mul2(bfpair(u23), SCL2P);
                float x0, x1, y0, y1;
                up2(ta, x0, x1);
                up2(tb, y0, y1);
                A0 = add2(A0, pk2(ex2f(x0), ex2f(x1)));
                A1 = add2(A1, pk2(ex2f(y0), ex2f(y1)));
            }
            float e0, e1, f0, f1;
            up2(A0, e0, e1);
            up2(A1, f0, f1);
            l0 += e0 + e1;
            l1 += f0 + f1;
        }
    }
    l0 += __shfl_xor_sync(0xffffffffu, l0, 1);
    l0 += __shfl_xor_sync(0xffffffffu, l0, 2);
    l1 += __shfl_xor_sync(0xffffffffu, l1, 1);
    l1 += __shfl_xor_sync(0xffffffffu, l1, 2);

    if ((lane & 3) == 0) {
        int qgrp = lane >> 2;
        int n0 = mblk * 128 + warp * 16 + qgrp;
        float* gl = g_l2 + (size_t)half * BHN + (size_t)bh * Ndim;
        gl[n0]     = l0;     // raw partial sum
        gl[n0 + 8] = l1;
    }
}

// ===================== PASS 2 kernel: P = bf16(2^(t-L)), O = P V =====================
__global__ __launch_bounds__(256, 2) void pass2_kernel(float* __restrict__ out, int bhbase) {
    extern __shared__ __align__(16) __nv_bfloat16 smem[];
    __nv_bfloat16* sQ  = smem;
    __nv_bfloat16* sK0 = smem + QELEMS;
    __nv_bfloat16* sK1 = sK0 + TELEMS;
    __nv_bfloat16* sV0 = sK1 + TELEMS;
    __nv_bfloat16* sV1 = sV0 + TELEMS;

    const int tid  = threadIdx.x;
    const int warp = tid >> 5;
    const int lane = tid & 31;
    const int mblk = blockIdx.x;
    const int bh   = blockIdx.y + bhbase;

    const __nv_bfloat16* Qg = g_q + (size_t)bh * Ndim * Ddim + (size_t)mblk * 128 * Ddim;
    const __nv_bfloat16* Kg = g_k + (size_t)bh * Ndim * Ddim;
    const __nv_bfloat16* Vg = g_v + (size_t)bh * Ndim * Ddim;

    const int krow = lane & 7;
    const int kc8  = (lane >> 3) & 3;
    const int vrow = lane & 15;
    const int vcsel = (lane & 16) ? 8 : 0;
    const unsigned kfragoff = (unsigned)((krow * SQ + kc8 * 8) * 2);
    const unsigned vfragoff = (unsigned)((vrow * SQ + vcsel) * 2);
    const unsigned kA[2] = { su(sK0) + kfragoff, su(sK1) + kfragoff };
    const unsigned vA[2] = { su(sV0) + vfragoff, su(sV1) + vfragoff };

    const int srow = tid >> 3, scol = tid & 7;
    const unsigned stoff0 = (unsigned)((srow * SQ + scol * 8) * 2);
    const unsigned stoff1 = stoff0 + (unsigned)(32 * SQ * 2);
    const unsigned dKs[2][2] = { { su(sK0) + stoff0, su(sK0) + stoff1 },
                                 { su(sK1) + stoff0, su(sK1) + stoff1 } };
    const unsigned dVs[2][2] = { { su(sV0) + stoff0, su(sV0) + stoff1 },
                                 { su(sV1) + stoff0, su(sV1) + stoff1 } };
    const char* gKt = (const char*)Kg + tid * 16;
    const char* gVt = (const char*)Vg + tid * 16;

    const int qgrp = lane >> 2;

    // row denominators: sum the two half-K partials (fixed order -> deterministic)
    const size_t lidx = (size_t)bh * Ndim + mblk * 128 + warp * 16 + qgrp;
    const float nL0 = -__log2f(g_l2[lidx] + g_l2[BHN + lidx]);
    const float nL1 = -__log2f(g_l2[lidx + 8] + g_l2[BHN + lidx + 8]);
    const uint64_t SCL2P = pk2(SCL2, SCL2);
    const uint64_t NL0P  = pk2(nL0, nL0);
    const uint64_t NL1P  = pk2(nL1, nL1);

    // stage Q + K0 + V0
    {
        const char* src = (const char*)Qg;
        unsigned qdst = su(sQ) + stoff0;
        #pragma unroll
        for (int it = 0; it < 4; it++)
            cp_async16s(qdst + it * (unsigned)(32 * SQ * 2), src + tid * 16 + it * 4096);
        cp_async16s(dKs[0][0], gKt);
        cp_async16s(dKs[0][1], gKt + 4096);
        cp_async16s(dVs[0][0], gVt);
        cp_async16s(dVs[0][1], gVt + 4096);
        CP_COMMIT();
        gKt += TBYTES; gVt += TBYTES;
    }
    CP_WAIT0();
    __syncthreads();

    uint32_t qa[4][4];
    {
        int rofs = warp * 16 + (lane & 15);
        int cofs = (lane & 16) ? 8 : 0;
        unsigned qaddr = su(sQ) + (unsigned)((rofs * SQ + cofs) * 2);
        #pragma unroll
        for (int kk = 0; kk < 4; kk++)
            ldsm_x4(qa[kk], qaddr + kk * 32);
    }

    float oa[8][4];
    #pragma unroll
    for (int u = 0; u < 8; u++)
        #pragma unroll
        for (int x = 0; x < 4; x++) oa[u][x] = 0.f;

    for (int kt = 0; kt < 32; kt++) {
        if (kt > 0) { CP_WAIT0(); __syncthreads(); }
        if (kt + 1 < 32) {
            const unsigned* dK = dKs[(kt + 1) & 1];
            const unsigned* dV = dVs[(kt + 1) & 1];
            cp_async16s(dK[0], gKt);
            cp_async16s(dK[1], gKt + 4096);
            cp_async16s(dV[0], gVt);
            cp_async16s(dV[1], gVt + 4096);
            CP_COMMIT();
            gKt += TBYTES; gVt += TBYTES;
        }
        const unsigned ka = kA[kt & 1];
        const unsigned va = vA[kt & 1];

        float sc[8][4];
        #pragma unroll
        for (int nt = 0; nt < 8; nt++)
            #pragma unroll
            for (int x = 0; x < 4; x++) sc[nt][x] = 0.f;

        #pragma unroll
        for (int nt = 0; nt < 8; nt++) {
            #pragma unroll
            for (int kh = 0; kh < 2; kh++) {
                uint32_t kb[4];
                ldsm_x4(kb, ka + (unsigned)(nt * 8 * SQ * 2 + kh * 64));
                mma16816(sc[nt], qa[2*kh][0], qa[2*kh][1], qa[2*kh][2], qa[2*kh][3], kb[0], kb[1]);
                mma16816(sc[nt], qa[2*kh+1][0], qa[2*kh+1][1], qa[2*kh+1][2], qa[2*kh+1][3], kb[2], kb[3]);
            }
        }

        uint32_t pA[8][2];
        #pragma unroll
        for (int nt = 0; nt < 8; nt++) {
            uint32_t u01 = pack_bf2(sc[nt][0], sc[nt][1]);
            uint32_t u23 = pack_bf2(sc[nt][2], sc[nt][3]);
            uint64_t ta = fma2(bfpair(u01), SCL2P, NL0P);
            uint64_t tb = fma2(bfpair(u23), SCL2P, NL1P);
            float x0, x1, y0, y1;
            up2(ta, x0, x1);
            up2(tb, y0, y1);
            pA[nt][0] = pack_bf2(ex2f(x0), ex2f(x1));
            pA[nt][1] = pack_bf2(ex2f(y0), ex2f(y1));
        }

        #pragma unroll
        for (int j = 0; j < 4; j++) {
            uint32_t A0 = pA[2*j][0], A1 = pA[2*j][1];
            uint32_t A2 = pA[2*j+1][0], A3 = pA[2*j+1][1];
            #pragma unroll
            for (int up = 0; up < 4; up++) {
                uint32_t vb[4];
                ldsm_x4_t(vb, va + (unsigned)(j * 16 * SQ * 2 + up * 32));
                mma16816(oa[2*up],     A0, A1, A2, A3, vb[0], vb[1]);
                mma16816(oa[2*up + 1], A0, A1, A2, A3, vb[2], vb[3]);
            }
        }
    }

    // epilogue: bf16-round O, store as float32 in [B,N,H*D]
    int b = bh >> 4, h = bh & 15;
    int n0 = mblk * 128 + warp * 16 + qgrp;
    size_t base0 = ((size_t)b * Ndim + n0) * (Hdim * Ddim) + (size_t)h * Ddim;
    size_t base1 = base0 + (size_t)8 * (Hdim * Ddim);
    const int tq = lane & 3;
    #pragma unroll
    for (int u = 0; u < 8; u++) {
        int d = u * 8 + 2 * tq;
        float2 w0 = { rb(oa[u][0]), rb(oa[u][1]) };
        float2 w1 = { rb(oa[u][2]), rb(oa[u][3]) };
        *(float2*)(out + base0 + d) = w0;
        *(float2*)(out + base1 + d) = w1;
    }
}

// ---------------- stream/event resources (created at static init; no device mem) ----------------
struct StreamRes {
    cudaStream_t s1 = nullptr;
    cudaEvent_t evFork = nullptr, evJoin = nullptr;
    bool ok = false;
    StreamRes() {
        if (cudaStreamCreateWithFlags(&s1, cudaStreamNonBlocking) == cudaSuccess &&
            cudaEventCreateWithFlags(&evFork, cudaEventDisableTiming) == cudaSuccess &&
            cudaEventCreateWithFlags(&evJoin, cudaEventDisableTiming) == cudaSuccess)
            ok = true;
    }
};
static StreamRes g_sr;

// ---------------- launch ----------------
extern "C" void kernel_launch(void* const* d_in, const int* in_sizes, int n_in,
                              void* d_out, int out_size) {
    (void)in_sizes; (void)n_in; (void)out_size;
    const float* q = (const float*)d_in[0];
    const float* k = (const float*)d_in[1];
    const float* v = (const float*)d_in[2];
    float* out = (float*)d_out;

    cudaFuncSetAttribute(pass1_kernel, cudaFuncAttributeMaxDynamicSharedMemorySize, SMEMB1);
    cudaFuncSetAttribute(pass2_kernel, cudaFuncAttributeMaxDynamicSharedMemorySize, SMEMB2);

    cvt_kernel<<<TOTE / 1024, 256>>>(q, k, v);

    const int BH = Bdim * Hdim;          // 64
    if (g_sr.ok) {
        // fork: half B on stream s1, half A on the launch stream
        cudaEventRecord(g_sr.evFork, 0);
        cudaStreamWaitEvent(g_sr.s1, g_sr.evFork, 0);

        dim3 grid1(Ndim / 128, BH / 2, 2);
        dim3 grid2(Ndim / 128, BH / 2);
        pass1_kernel<<<grid1, 256, SMEMB1>>>(0);
        pass1_kernel<<<grid1, 256, SMEMB1, g_sr.s1>>>(BH / 2);
        pass2_kernel<<<grid2, 256, SMEMB2>>>(out, 0);
        pass2_kernel<<<grid2, 256, SMEMB2, g_sr.s1>>>(out, BH / 2);

        // join
        cudaEventRecord(g_sr.evJoin, g_sr.s1);
        cudaStreamWaitEvent(0, g_sr.evJoin, 0);
    } else {
        dim3 grid1(Ndim / 128, BH, 2);
        dim3 grid2(Ndim / 128, BH);
        pass1_kernel<<<grid1, 256, SMEMB1>>>(0);
        pass2_kernel<<<grid2, 256, SMEMB2>>>(out, 0);
    }
}